// round 13
// baseline (speedup 1.0000x reference)
#include <cuda_runtime.h>
#include <cuda_bf16.h>
#include <math.h>
#include <cstdint>

// ---------------------------------------------------------------------------
// HanningTemplateLayer as band-aligned Toeplitz GEMM on mma.sync (bf16 hi/lo).
// CTA = 128 output columns x 32 batch rows.  grid = (512 tiles, 2 row-halves).
//   D[m,n] = sum_k T[m,k] * X[n,k];  T[m,k] = c[k-m];  X[n,k] = x[rb+n, col0-40+k]
//   out[rb+n, col0+m] = D[m,n]
// Warp w owns m in [16w,16w+16); band spans k in [16w,16w+96): 6 k16-steps.
// 3 products: Ah*Bh + Ah*Bl + Al*Bh (fp32 accumulate), rel_err ~4e-6.
// R13: direct parallel coeff->pair-table compute (1 barrier, no scratch race),
//      coalesced epilogue via smem transpose (reuses xhi region).
// ---------------------------------------------------------------------------

#define THREADS 256
#define TILE_M  128
#define ROWS    32
#define TAPS    80
#define HALF    40
#define L_LEN   65536
#define SROW    264          // uint16 per X row (528B; stride mod 128 = 16)
#define SROW2   132          // uint32 stride per X row
#define SDP     132          // float stride of transpose buffer row

// smem byte offsets
#define OFF_CPH   0                     // 112 x u32 hi pair table
#define OFF_CPL   512
#define OFF_XHI   1536                  // 32 rows x 528B  (reused as transpose buf)
#define OFF_XLO   (OFF_XHI + ROWS*528)
#define SM_TOTAL  (OFF_XLO + ROWS*528)  // 35328 B

__device__ __forceinline__ void mma_bf16(float* d, uint32_t a0, uint32_t a1,
                                         uint32_t a2, uint32_t a3,
                                         uint32_t b0, uint32_t b1) {
    asm("mma.sync.aligned.m16n8k16.row.col.f32.bf16.bf16.f32 "
        "{%0,%1,%2,%3}, {%4,%5,%6,%7}, {%8,%9}, {%0,%1,%2,%3};"
        : "+f"(d[0]), "+f"(d[1]), "+f"(d[2]), "+f"(d[3])
        : "r"(a0), "r"(a1), "r"(a2), "r"(a3), "r"(b0), "r"(b1));
}

// pack two f32 -> bf16x2 {lo half: a, hi half: b}
__device__ __forceinline__ uint32_t bfpack(float a, float b) {
    uint32_t r;
    asm("cvt.rn.bf16x2.f32 %0, %1, %2;" : "=r"(r) : "f"(b), "f"(a));
    return r;
}

__device__ __forceinline__ uint16_t bfbits(__nv_bfloat16 h) {
    return *reinterpret_cast<uint16_t*>(&h);
}

// combined Hann filter tap, zero outside [0, 80)
__device__ __forceinline__ float tap(int t, const float* p) {
    const int widths[4] = { 10, 20, 30, 40 };
    int dd = t - HALF;
    float c = 0.0f;
    #pragma unroll
    for (int i = 0; i < 4; ++i) {
        int w = widths[i], k = dd + w;
        if (k >= 0 && k < 2 * w) {
            float h = 0.5f - 0.5f * cosf(6.283185307179586f * (float)k
                                         / (float)(2 * w - 1));
            c = fmaf(p[i], h, c);
        }
    }
    return c;
}

__global__ __launch_bounds__(THREADS, 4)
void hann_mma_kernel(const float* __restrict__ x, const float* __restrict__ tw,
                     float* __restrict__ out) {
    extern __shared__ __align__(16) char smem[];
    uint32_t* cph = reinterpret_cast<uint32_t*>(smem + OFF_CPH);
    uint32_t* cpl = reinterpret_cast<uint32_t*>(smem + OFF_CPL);
    uint16_t* xhi = reinterpret_cast<uint16_t*>(smem + OFF_XHI);
    uint16_t* xlo = reinterpret_cast<uint16_t*>(smem + OFF_XLO);

    const int tid  = threadIdx.x;
    const int col0 = blockIdx.x * TILE_M;
    const int rb   = blockIdx.y * ROWS;       // batch-row base of this CTA

    // -- X tile fill: 32 rows x 26 oct-chunks; fp32 -> bf16 hi/lo (vectorized) --
    #pragma unroll
    for (int it = 0; it < 4; ++it) {
        int idx = tid + it * THREADS;            // < 1024
        if (idx < ROWS * 26) {
            int row = idx / 26;
            int c8  = idx - row * 26;
            int kk  = c8 * 8;
            int g   = col0 - HALF + kk;          // 4-aligned
            const float* xr = x + (size_t)(rb + row) * L_LEN;
            float4 va, vb;
            if (g >= 0 && g + 8 <= L_LEN) {
                va = *reinterpret_cast<const float4*>(xr + g);
                vb = *reinterpret_cast<const float4*>(xr + g + 4);
            } else {
                float tp[8];
                #pragma unroll
                for (int e = 0; e < 8; ++e) {
                    int ge = g + e;
                    tp[e] = (ge >= 0 && ge < L_LEN) ? xr[ge] : 0.0f;
                }
                va = make_float4(tp[0], tp[1], tp[2], tp[3]);
                vb = make_float4(tp[4], tp[5], tp[6], tp[7]);
            }
            uint32_t h01 = bfpack(va.x, va.y), h23 = bfpack(va.z, va.w);
            uint32_t h45 = bfpack(vb.x, vb.y), h67 = bfpack(vb.z, vb.w);
            float l0 = va.x - __uint_as_float(h01 << 16);
            float l1 = va.y - __uint_as_float(h01 & 0xFFFF0000u);
            float l2 = va.z - __uint_as_float(h23 << 16);
            float l3 = va.w - __uint_as_float(h23 & 0xFFFF0000u);
            float l4 = vb.x - __uint_as_float(h45 << 16);
            float l5 = vb.y - __uint_as_float(h45 & 0xFFFF0000u);
            float l6 = vb.z - __uint_as_float(h67 << 16);
            float l7 = vb.w - __uint_as_float(h67 & 0xFFFF0000u);
            uint32_t q01 = bfpack(l0, l1), q23 = bfpack(l2, l3);
            uint32_t q45 = bfpack(l4, l5), q67 = bfpack(l6, l7);
            uint32_t eoff = row * SROW + kk;     // element offset, 8-aligned
            *reinterpret_cast<uint4*>(xhi + eoff) = make_uint4(h01, h23, h45, h67);
            *reinterpret_cast<uint4*>(xlo + eoff) = make_uint4(q01, q23, q45, q67);
        }
    }

    // -- pair tables computed directly & in parallel: cp*[i]=(c(i-16),c(i-15)) --
    if (tid < 112) {
        float w0 = tw[0], w1 = tw[1], w2 = tw[2], w3 = tw[3];
        float mx = fmaxf(fmaxf(w0, w1), fmaxf(w2, w3));
        float e0 = expf(w0 - mx), e1 = expf(w1 - mx);
        float e2 = expf(w2 - mx), e3 = expf(w3 - mx);
        float s  = 1.0f / (e0 + e1 + e2 + e3);
        float p[4] = { e0 * s, e1 * s, e2 * s, e3 * s };
        float ca = tap(tid - 16, p);
        float cb = tap(tid - 15, p);
        __nv_bfloat16 cah = __float2bfloat16(ca);
        __nv_bfloat16 cbh = __float2bfloat16(cb);
        __nv_bfloat16 cal = __float2bfloat16(ca - __bfloat162float(cah));
        __nv_bfloat16 cbl = __float2bfloat16(cb - __bfloat162float(cbh));
        cph[tid] = (uint32_t)bfbits(cbh) << 16 | bfbits(cah);
        cpl[tid] = (uint32_t)bfbits(cbl) << 16 | bfbits(cal);
    }
    __syncthreads();

    // -- band-aligned MMA: warp w -> m in [16w,16w+16), k in [16w,16w+96) ------
    const int wid = tid >> 5;
    const int lid = tid & 31;
    const int g   = lid >> 2;                 // group (row / n within frag)
    const int t   = lid & 3;                  // thread-in-group
    const int wm0 = wid * 16;

    float d[4][4];
    #pragma unroll
    for (int nfi = 0; nfi < 4; ++nfi)
        #pragma unroll
        for (int r = 0; r < 4; ++r) d[nfi][r] = 0.0f;

    #pragma unroll
    for (int s = 0; s < 6; ++s) {
        // A fragments: ah3 == ah0, al3 == al0 (Toeplitz row shift)
        const int base = 16 + 16 * s + 2 * t - g;
        uint32_t ah0 = cph[base];
        uint32_t ah1 = cph[base - 8];
        uint32_t ah2 = cph[base + 8];
        uint32_t al0 = cpl[base];
        uint32_t al1 = cpl[base - 8];
        uint32_t al2 = cpl[base + 8];

        const int ki = ((wm0 + 16 * s) >> 1) + t;   // uint32 index of k+2t

        // load ALL B fragments for this k-step first
        uint32_t bh0[4], bh1[4], bl0[4], bl1[4];
        #pragma unroll
        for (int nfi = 0; nfi < 4; ++nfi) {
            const int n = nfi * 8 + g;
            const uint32_t* ph = reinterpret_cast<const uint32_t*>(xhi) + n * SROW2;
            const uint32_t* pl = reinterpret_cast<const uint32_t*>(xlo) + n * SROW2;
            bh0[nfi] = ph[ki]; bh1[nfi] = ph[ki + 4];
            bl0[nfi] = pl[ki]; bl1[nfi] = pl[ki + 4];
        }

        // product-major MMA stream: same-acc dependency distance = 4
        #pragma unroll
        for (int nfi = 0; nfi < 4; ++nfi)
            mma_bf16(d[nfi], ah0, ah1, ah2, ah0, bh0[nfi], bh1[nfi]);
        #pragma unroll
        for (int nfi = 0; nfi < 4; ++nfi)
            mma_bf16(d[nfi], ah0, ah1, ah2, ah0, bl0[nfi], bl1[nfi]);
        #pragma unroll
        for (int nfi = 0; nfi < 4; ++nfi)
            mma_bf16(d[nfi], al0, al1, al2, al0, bh0[nfi], bh1[nfi]);
    }

    // -- epilogue: transpose through smem, then coalesced float4 row writes ----
    __syncthreads();                            // mainloop done; xhi reusable
    float* sd = reinterpret_cast<float*>(smem + OFF_XHI);  // [32][SDP]
    #pragma unroll
    for (int nfi = 0; nfi < 4; ++nfi) {
        const int n0 = nfi * 8 + 2 * t;
        sd[n0 * SDP + wm0 + g]           = d[nfi][0];
        sd[(n0 + 1) * SDP + wm0 + g]     = d[nfi][1];
        sd[n0 * SDP + wm0 + g + 8]       = d[nfi][2];
        sd[(n0 + 1) * SDP + wm0 + g + 8] = d[nfi][3];
    }
    __syncthreads();
    #pragma unroll
    for (int it = 0; it < 4; ++it) {
        int item = tid + it * THREADS;          // < 1024
        int row  = item >> 5;                   // 0..31
        int f4   = item & 31;                   // 0..31 float4 within row
        float4 v = *reinterpret_cast<const float4*>(sd + row * SDP + 4 * f4);
        *reinterpret_cast<float4*>(out + (size_t)(rb + row) * L_LEN
                                       + col0 + 4 * f4) = v;
    }
}

extern "C" void kernel_launch(void* const* d_in, const int* in_sizes, int n_in,
                              void* d_out, int out_size) {
    const float* x  = (const float*)d_in[0];   // [64, 65536] fp32
    const float* tw = (const float*)d_in[1];   // [4] fp32
    float* out = (float*)d_out;

    cudaFuncSetAttribute(hann_mma_kernel,
                         cudaFuncAttributeMaxDynamicSharedMemorySize, SM_TOTAL);
    dim3 grid(L_LEN / TILE_M, 64 / ROWS);      // (512, 2) = 1024 CTAs
    hann_mma_kernel<<<grid, THREADS, SM_TOTAL>>>(x, tw, out);
}